// round 1
// baseline (speedup 1.0000x reference)
#include <cuda_runtime.h>
#include <math.h>
#include <stdint.h>

#define Bsz 8192
#define Tt  128
#define Ef  128
#define Hh  128
#define Gg  512
#define Do  5

// ---------------- device scratch (static: no allocations allowed) ----------------
// gates_x for t in [0,64) and [64,128): each 64*8192*512 floats = 1 GB
__device__ float g_gx0[64 * 8192 * 512];
__device__ float g_gx1[64 * 8192 * 512];
__device__ float g_h[Bsz * Hh];
__device__ float g_c[Bsz * Hh];
__device__ float g_gates[Bsz * Gg];
__device__ float g_y[(size_t)Tt * Bsz * Do];     // 20 MB, pre-BN outputs
__device__ float g_s[Tt * Ef * 3];               // folded emb-BN affine coeffs
__device__ float g_ymean[Tt * Do];
__device__ float g_yrstd[Tt * Do];

// ---------------- K0: zero h, c ----------------
__global__ void k_zero_hc() {
    int i = blockIdx.x * 256 + threadIdx.x;
    if (i < Bsz * Hh) { g_h[i] = 0.0f; g_c[i] = 0.0f; }
}

// ---------------- K1: per-t emb BN stats via exact x-moments ----------------
// z = x0*W0 + x1*W1 + b is linear in x, so mean/var of z over the batch are
// exact bilinear forms of the 5 batch moments of (x0, x1).
__global__ void k_emb_stats(const float* __restrict__ x,
                            const float* __restrict__ W_emb,
                            const float* __restrict__ b_emb,
                            const float* __restrict__ gamma,
                            const float* __restrict__ beta) {
    int t = blockIdx.x;
    int tid = threadIdx.x;
    float m0 = 0.f, m1 = 0.f, m00 = 0.f, m11 = 0.f, m01 = 0.f;
    for (int b = tid; b < Bsz; b += 256) {
        size_t xi = ((size_t)b * Tt + t) * 2;
        float x0 = x[xi], x1 = x[xi + 1];
        m0 += x0; m1 += x1; m00 += x0 * x0; m11 += x1 * x1; m01 += x0 * x1;
    }
    const unsigned FULL = 0xffffffffu;
    #pragma unroll
    for (int off = 16; off; off >>= 1) {
        m0  += __shfl_xor_sync(FULL, m0,  off);
        m1  += __shfl_xor_sync(FULL, m1,  off);
        m00 += __shfl_xor_sync(FULL, m00, off);
        m11 += __shfl_xor_sync(FULL, m11, off);
        m01 += __shfl_xor_sync(FULL, m01, off);
    }
    __shared__ float sw[8][5];
    __shared__ float mom[5];
    int warp = tid >> 5, lane = tid & 31;
    if (lane == 0) {
        sw[warp][0] = m0; sw[warp][1] = m1; sw[warp][2] = m00;
        sw[warp][3] = m11; sw[warp][4] = m01;
    }
    __syncthreads();
    if (tid < 5) {
        float s = 0.f;
        #pragma unroll
        for (int w = 0; w < 8; w++) s += sw[w][tid];
        mom[tid] = s * (1.0f / Bsz);
    }
    __syncthreads();
    if (tid < Ef) {
        float mx0 = mom[0], mx1 = mom[1];
        float vx0 = mom[2] - mx0 * mx0;
        float vx1 = mom[3] - mx1 * mx1;
        float cxy = mom[4] - mx0 * mx1;
        float w0 = W_emb[tid * 2], w1 = W_emb[tid * 2 + 1];
        float mu  = w0 * mx0 + w1 * mx1 + b_emb[tid];
        float var = w0 * w0 * vx0 + 2.0f * w0 * w1 * cxy + w1 * w1 * vx1;
        float rstd = rsqrtf(var + 1e-5f);
        float gr = gamma[tid] * rstd;
        int o = (t * Ef + tid) * 3;
        g_s[o + 0] = gr * w0;
        g_s[o + 1] = gr * w1;
        g_s[o + 2] = gr * (b_emb[tid] - mu) + beta[tid];
    }
}

// ---------------- K2: gates_x = relu(BN(emb)) @ W_ih^T + b_ih  (parallel) ----------
// Tile 128(M) x 64(N), K=128 fully resident. e computed on the fly from x + g_s.
#define SMEM_GX_FLOATS (16384 + 128 * 65 + 256 + 384)
__global__ void k_gx_gemm(const float* __restrict__ x,
                          const float* __restrict__ W_ih,
                          const float* __restrict__ b_ih) {
    extern __shared__ float sm[];
    float* As = sm;                       // [k=128][r=128]
    float* Bs = sm + 16384;               // [k=128][c=64] pad 65
    float* xs = sm + 16384 + 128 * 65;    // [128][2]
    float* ss = xs + 256;                 // [128][3]
    int tid = threadIdx.x;
    int t  = blockIdx.y >> 6;
    int b0 = (blockIdx.y & 63) << 7;
    int n0 = blockIdx.x << 6;

    if (tid < 128) {
        size_t xi = ((size_t)(b0 + tid) * Tt + t) * 2;
        xs[tid * 2]     = x[xi];
        xs[tid * 2 + 1] = x[xi + 1];
        int o = (t * Ef + tid) * 3;
        ss[tid * 3]     = g_s[o];
        ss[tid * 3 + 1] = g_s[o + 1];
        ss[tid * 3 + 2] = g_s[o + 2];
    }
    __syncthreads();
    for (int idx = tid; idx < 128 * 128; idx += 256) {
        int j = idx >> 7, r = idx & 127;
        float e = fmaf(ss[j * 3], xs[r * 2], fmaf(ss[j * 3 + 1], xs[r * 2 + 1], ss[j * 3 + 2]));
        As[j * 128 + r] = fmaxf(e, 0.0f);
    }
    for (int idx = tid; idx < 128 * 64; idx += 256) {
        int k = idx & 127, c = idx >> 7;
        Bs[k * 65 + c] = W_ih[(size_t)(n0 + c) * Ef + k];
    }
    __syncthreads();

    int r0 = (tid >> 4) << 3;
    int c0 = (tid & 15) << 2;
    float acc[8][4];
    #pragma unroll
    for (int i = 0; i < 8; i++)
        #pragma unroll
        for (int j = 0; j < 4; j++) acc[i][j] = 0.0f;

    #pragma unroll 4
    for (int k = 0; k < 128; k++) {
        float4 a0 = *(const float4*)&As[k * 128 + r0];
        float4 a1 = *(const float4*)&As[k * 128 + r0 + 4];
        float av[8] = {a0.x, a0.y, a0.z, a0.w, a1.x, a1.y, a1.z, a1.w};
        float bv[4];
        #pragma unroll
        for (int j = 0; j < 4; j++) bv[j] = Bs[k * 65 + c0 + j];
        #pragma unroll
        for (int i = 0; i < 8; i++)
            #pragma unroll
            for (int j = 0; j < 4; j++) acc[i][j] = fmaf(av[i], bv[j], acc[i][j]);
    }

    float4 bia = *(const float4*)&b_ih[n0 + c0];
    float* gx = (t < 64) ? g_gx0 : g_gx1;
    size_t tb = (size_t)(t & 63) * Bsz;
    #pragma unroll
    for (int i = 0; i < 8; i++) {
        size_t o = (tb + b0 + r0 + i) * Gg + n0 + c0;
        float4 v = make_float4(acc[i][0] + bia.x, acc[i][1] + bia.y,
                               acc[i][2] + bia.z, acc[i][3] + bia.w);
        *(float4*)&gx[o] = v;
    }
}

// ---------------- K3: per-step recurrent GEMM: gates = h@W_hh^T + b_hh + gates_x[t] --
#define SMEM_REC_FLOATS (128 * 129 + 128 * 65)
__global__ void k_rec_gemm(const float* __restrict__ W_hh,
                           const float* __restrict__ b_hh, int t) {
    extern __shared__ float sm[];
    float* As = sm;                 // [k=128][r=128] pad 129
    float* Bs = sm + 128 * 129;     // [k=128][c=64] pad 65
    int tid = threadIdx.x;
    int b0 = blockIdx.y << 7;
    int n0 = blockIdx.x << 6;

    for (int idx = tid; idx < 128 * 128; idx += 256) {
        int k = idx & 127, r = idx >> 7;
        As[k * 129 + r] = g_h[(size_t)(b0 + r) * Hh + k];
    }
    for (int idx = tid; idx < 128 * 64; idx += 256) {
        int k = idx & 127, c = idx >> 7;
        Bs[k * 65 + c] = W_hh[(size_t)(n0 + c) * Hh + k];
    }
    __syncthreads();

    int r0 = (tid >> 4) << 3;
    int c0 = (tid & 15) << 2;
    float acc[8][4];
    #pragma unroll
    for (int i = 0; i < 8; i++)
        #pragma unroll
        for (int j = 0; j < 4; j++) acc[i][j] = 0.0f;

    #pragma unroll 4
    for (int k = 0; k < 128; k++) {
        float av[8], bv[4];
        #pragma unroll
        for (int i = 0; i < 8; i++) av[i] = As[k * 129 + r0 + i];
        #pragma unroll
        for (int j = 0; j < 4; j++) bv[j] = Bs[k * 65 + c0 + j];
        #pragma unroll
        for (int i = 0; i < 8; i++)
            #pragma unroll
            for (int j = 0; j < 4; j++) acc[i][j] = fmaf(av[i], bv[j], acc[i][j]);
    }

    const float* gx = (t < 64) ? g_gx0 : g_gx1;
    size_t tb = (size_t)(t & 63) * Bsz;
    float4 bh = *(const float4*)&b_hh[n0 + c0];
    #pragma unroll
    for (int i = 0; i < 8; i++) {
        int row = b0 + r0 + i;
        float4 gv = *(const float4*)&gx[(tb + row) * Gg + n0 + c0];
        float4 v = make_float4(acc[i][0] + bh.x + gv.x, acc[i][1] + bh.y + gv.y,
                               acc[i][2] + bh.z + gv.z, acc[i][3] + bh.w + gv.w);
        *(float4*)&g_gates[(size_t)row * Gg + n0 + c0] = v;
    }
}

// ---------------- K4: LSTM cell + fused y = h@W_out^T (pre-BN; b_out cancels) -------
__global__ void k_cell(const float* __restrict__ W_out, int t) {
    int b = blockIdx.x;
    int j = threadIdx.x;  // 128
    __shared__ float Ws[Do * Hh];
    __shared__ float part[4][Do];
    for (int i = j; i < Do * Hh; i += 128) Ws[i] = W_out[i];

    size_t gb = (size_t)b * Gg;
    float ig = g_gates[gb + j];
    float fg = g_gates[gb + Hh + j];
    float gg = g_gates[gb + 2 * Hh + j];
    float og = g_gates[gb + 3 * Hh + j];
    float c  = g_c[b * Hh + j];
    __syncthreads();

    float si = 1.0f / (1.0f + expf(-ig));
    float sf = 1.0f / (1.0f + expf(-fg));
    float so = 1.0f / (1.0f + expf(-og));
    float cn = sf * c + si * tanhf(gg);
    float hn = so * tanhf(cn);
    g_c[b * Hh + j] = cn;
    g_h[b * Hh + j] = hn;

    const unsigned FULL = 0xffffffffu;
    #pragma unroll
    for (int f = 0; f < Do; f++) {
        float v = hn * Ws[f * Hh + j];
        #pragma unroll
        for (int off = 16; off; off >>= 1) v += __shfl_xor_sync(FULL, v, off);
        if ((j & 31) == 0) part[j >> 5][f] = v;
    }
    __syncthreads();
    if (j < Do) {
        float s = part[0][j] + part[1][j] + part[2][j] + part[3][j];
        g_y[((size_t)t * Bsz + b) * Do + j] = s;
    }
}

// ---------------- K5: per-(t, f) output BN stats ----------------
__global__ void k_ystats() {
    int tf = blockIdx.x;
    int t = tf / Do, f = tf % Do;
    int tid = threadIdx.x;
    float s = 0.f, q = 0.f;
    for (int b = tid; b < Bsz; b += 256) {
        float v = g_y[((size_t)t * Bsz + b) * Do + f];
        s += v; q += v * v;
    }
    const unsigned FULL = 0xffffffffu;
    #pragma unroll
    for (int off = 16; off; off >>= 1) {
        s += __shfl_xor_sync(FULL, s, off);
        q += __shfl_xor_sync(FULL, q, off);
    }
    __shared__ float sws[8], swq[8];
    int warp = tid >> 5, lane = tid & 31;
    if (lane == 0) { sws[warp] = s; swq[warp] = q; }
    __syncthreads();
    if (tid == 0) {
        float S = 0.f, Q = 0.f;
        #pragma unroll
        for (int w = 0; w < 8; w++) { S += sws[w]; Q += swq[w]; }
        float mean = S * (1.0f / Bsz);
        float var = Q * (1.0f / Bsz) - mean * mean;
        g_ymean[t * Do + f] = mean;
        g_yrstd[t * Do + f] = rsqrtf(var + 1e-5f);
    }
}

// ---------------- K6: normalize y -> out[b, t, f] ----------------
__global__ void k_ynorm(const float* __restrict__ gamma,
                        const float* __restrict__ beta,
                        float* __restrict__ out) {
    size_t i = (size_t)blockIdx.x * 256 + threadIdx.x;
    if (i >= (size_t)Bsz * Tt * Do) return;
    int f = (int)(i % Do);
    size_t bt = i / Do;
    int t = (int)(bt % Tt);
    size_t b = bt / Tt;
    float m = g_ymean[t * Do + f], r = g_yrstd[t * Do + f];
    float v = g_y[((size_t)t * Bsz + b) * Do + f];
    out[i] = gamma[f] * (v - m) * r + beta[f];
}

// ---------------- K7: final h, c -> out tail ----------------
__global__ void k_copy_hc(float* __restrict__ out) {
    int i = blockIdx.x * 256 + threadIdx.x;
    if (i < Bsz * Hh) {
        const size_t OFF_H = (size_t)Bsz * Tt * Do;
        out[OFF_H + i] = g_h[i];
        out[OFF_H + Bsz * Hh + i] = g_c[i];
    }
}

// ---------------- launch ----------------
extern "C" void kernel_launch(void* const* d_in, const int* in_sizes, int n_in,
                              void* d_out, int out_size) {
    const float* x         = (const float*)d_in[0];
    const float* W_emb     = (const float*)d_in[1];
    const float* b_emb     = (const float*)d_in[2];
    const float* gamma_emb = (const float*)d_in[3];
    const float* beta_emb  = (const float*)d_in[4];
    const float* W_ih      = (const float*)d_in[5];
    const float* b_ih      = (const float*)d_in[6];
    const float* W_hh      = (const float*)d_in[7];
    const float* b_hh      = (const float*)d_in[8];
    const float* W_out     = (const float*)d_in[9];
    // d_in[10] = b_out: cancels exactly inside the output BatchNorm.
    const float* gamma_out = (const float*)d_in[11];
    const float* beta_out  = (const float*)d_in[12];
    float* out = (float*)d_out;

    const int SMEM_GX  = SMEM_GX_FLOATS * 4;
    const int SMEM_REC = SMEM_REC_FLOATS * 4;
    cudaFuncSetAttribute(k_gx_gemm,  cudaFuncAttributeMaxDynamicSharedMemorySize, SMEM_GX);
    cudaFuncSetAttribute(k_rec_gemm, cudaFuncAttributeMaxDynamicSharedMemorySize, SMEM_REC);

    k_zero_hc<<<(Bsz * Hh + 255) / 256, 256>>>();
    k_emb_stats<<<Tt, 256>>>(x, W_emb, b_emb, gamma_emb, beta_emb);
    k_gx_gemm<<<dim3(8, 8192), 256, SMEM_GX>>>(x, W_ih, b_ih);

    for (int t = 0; t < Tt; t++) {
        k_rec_gemm<<<dim3(8, 64), 256, SMEM_REC>>>(W_hh, b_hh, t);
        k_cell<<<Bsz, 128>>>(W_out, t);
    }

    k_ystats<<<Tt * Do, 256>>>();
    int n6 = Bsz * Tt * Do;
    k_ynorm<<<(n6 + 255) / 256, 256>>>(gamma_out, beta_out, out);
    k_copy_hc<<<(Bsz * Hh + 255) / 256, 256>>>(out);
}